// round 16
// baseline (speedup 1.0000x reference)
#include <cuda_runtime.h>
#include <cuda_fp16.h>
#include <cstdint>

#define CIN   672
#define COUT  128
#define HW    49
#define NPAD  56
#define KC    32
#define NKC   21
#define GRID  1024
#define THREADS 256

#define LDA 20            // A row stride (half2 words): conflict-free frag reads
#define LDB 24            // B row stride (half2 words)
#define A_WORDS (COUT*LDA)   // 2560
#define B_WORDS (NPAD*LDB)   // 1344

// word offsets in dynamic smem
#define OFF_SS 0                         // float2[672] = 1344 words
#define OFF_A0 1344
#define OFF_A1 (OFF_A0 + A_WORDS)
#define OFF_B0 (OFF_A1 + A_WORDS)
#define OFF_B1 (OFF_B0 + B_WORDS)
#define PIPE_WORDS (OFF_B1 + B_WORDS)    // 9152 words
#define PS 57
#define P_WORDS (COUT*PS)                // 7296 < PIPE_WORDS
#define SMEM_BYTES (PIPE_WORDS*4)        // 36608 B -> 3 CTAs/SM (109.8KB)

// ---- fp16 copy of W, produced once by K0 ----
__device__ __align__(16) __half W16_buf[COUT * CIN];

__global__ void w_cvt_kernel(const float* __restrict__ W) {
    int i = blockIdx.x * 256 + threadIdx.x;      // 84*256 = 21504 = 86016/4
    float4 v = *(const float4*)(W + i * 4);
    __half2 h0 = __floats2half2_rn(v.x, v.y);
    __half2 h1 = __floats2half2_rn(v.z, v.w);
    uint2 q;
    q.x = *(uint32_t*)&h0;
    q.y = *(uint32_t*)&h1;
    *(uint2*)(W16_buf + i * 4) = q;
}

__device__ __forceinline__ void hmma16816(float c[4],
    uint32_t a0, uint32_t a1, uint32_t a2, uint32_t a3, uint32_t b0, uint32_t b1)
{
    asm volatile(
        "mma.sync.aligned.m16n8k16.row.col.f32.f16.f16.f32 "
        "{%0,%1,%2,%3}, {%4,%5,%6,%7}, {%8,%9}, {%0,%1,%2,%3};"
        : "+f"(c[0]), "+f"(c[1]), "+f"(c[2]), "+f"(c[3])
        : "r"(a0), "r"(a1), "r"(a2), "r"(a3), "r"(b0), "r"(b1));
}
__device__ __forceinline__ uint32_t pack_h2(float lo, float hi) {
    __half2 h = __floats2half2_rn(lo, hi);
    return *reinterpret_cast<uint32_t*>(&h);
}
__device__ __forceinline__ uint32_t smem_u32(const void* p) {
    uint32_t a;
    asm("{ .reg .u64 t; cvta.to.shared.u64 t, %1; cvt.u32.u64 %0, t; }" : "=r"(a) : "l"(p));
    return a;
}
__device__ __forceinline__ void cp16(uint32_t dst, const void* src) {
    asm volatile("cp.async.cg.shared.global [%0], [%1], 16;" :: "r"(dst), "l"(src) : "memory");
}

extern __shared__ uint32_t sm[];

__global__ void __launch_bounds__(THREADS, 3)
bn_conv_nb1(const float* __restrict__ x,
            const float* __restrict__ gamma,
            const float* __restrict__ beta,
            const float* __restrict__ rmean,
            const float* __restrict__ rvar,
            float* __restrict__ out)
{
    const int tid  = threadIdx.x;
    const int wid  = tid >> 5;
    const int lane = tid & 31;
    const int g = lane >> 2, t = lane & 3;
    const int m0 = wid * 16;              // 8 warps over M=128, Mw=16
    const uint32_t sb = smem_u32(sm);

    float2* ssc = (float2*)(sm + OFF_SS);
    const float* sscf = (const float*)ssc;

    // ---- prologue: BN fold + zero B buffers (covers pad rows 49..55) ----
    for (int c = tid; c < CIN; c += THREADS) {
        float inv = rsqrtf(rvar[c] + 1e-5f);
        float s = gamma[c] * inv;
        ssc[c] = make_float2(s, beta[c] - rmean[c] * s);
    }
    for (int i = tid; i < 2 * B_WORDS; i += THREADS) sm[OFF_B0 + i] = 0u;

    // ---- per-thread staging constants: 392 pair-slots = 8p x 49n, 2 iters ----
    int xoff[2], bsk[2];                   // bsk = STS word offset | (kl<<20)
    #pragma unroll
    for (int j = 0; j < 2; j++) {
        int i = tid + j * THREADS;
        if (i > 391) i = 391;
        int p = i / HW;
        int n = i - HW * p;
        int tp = p & 3, ks = p >> 2;
        int kl = ks * 16 + tp * 2;
        xoff[j] = kl * HW + n;
        bsk[j]  = (n * LDB + 2 * ((p + ((n >> 2) & 7)) & 7)) | (kl << 20);
    }
    const bool v1 = (tid < 136);          // iter 1 valid for i<392

    // A cp.async: 512 quads = 128 m x 4 q, 2 per thread
    const int am0 = tid >> 2, aq0 = tid & 3;
    const int am1 = (tid + THREADS) >> 2, aq1 = (tid + THREADS) & 3;

    const float* xb = x + (size_t)blockIdx.x * CIN * HW;
    __syncthreads();

    float acc[7][4];
    #pragma unroll
    for (int nt = 0; nt < 7; nt++)
        #pragma unroll
        for (int i = 0; i < 4; i++) acc[nt][i] = 0.0f;

    const int ar  = (m0 + g) * LDA;       // rows g / g+8 via +8*LDA
    const int bnb = g * LDB;              // n0 = 0 (single n-group)
    const int csl = g >> 2;

    float xv[2][4];

    #pragma unroll 1
    for (int kc = -1; kc < NKC; kc++) {
        const int kcn = kc + 1;

        // ---- cp.async A(kcn) into the free buffer ----
        if (kcn < NKC) {
            const uint32_t abase = sb + ((kcn & 1) ? OFF_A1 : OFF_A0) * 4;
            cp16(abase + (am0 * LDA + aq0 * 4) * 4, W16_buf + am0 * CIN + aq0 * 8 + kcn * KC);
            cp16(abase + (am1 * LDA + aq1 * 4) * 4, W16_buf + am1 * CIN + aq1 * 8 + kcn * KC);
        }
        asm volatile("cp.async.commit_group;" ::: "memory");

        // ---- x LDGs for chunk kcn (BEFORE the MMA — latency hidden under it) ----
        if (kcn < NKC) {
            const int xadd = kcn * (KC * HW);
            #pragma unroll
            for (int j = 0; j < 2; j++) {
                if (j == 0 || v1) {
                    const float* px = xb + xoff[j] + xadd;
                    xv[j][0] = px[0];
                    xv[j][1] = px[HW];
                    xv[j][2] = px[8 * HW];
                    xv[j][3] = px[9 * HW];
                }
            }
        }

        // ---- MMA on chunk kc: 7 nt x 2 ks = 14 HMMA per warp ----
        if (kc >= 0) {
            const uint32_t* As = sm + ((kc & 1) ? OFF_A1 : OFF_A0);
            const uint32_t* Bs = sm + ((kc & 1) ? OFF_B1 : OFF_B0);
            #pragma unroll
            for (int ks = 0; ks < 2; ks++) {
                const int ka = ks * 8 + t;
                uint32_t a0[4];
                a0[0] = As[ar + ka];
                a0[1] = As[ar + 8 * LDA + ka];
                a0[2] = As[ar + ka + 4];
                a0[3] = As[ar + 8 * LDA + ka + 4];
                const int pr = ks * 4 + t;
                #pragma unroll
                for (int nt = 0; nt < 7; nt++) {
                    const int slot = (pr + csl + 2 * nt) & 7;
                    uint2 b = *(const uint2*)&Bs[bnb + nt * 8 * LDB + 2 * slot];
                    hmma16816(acc[nt], a0[0], a0[1], a0[2], a0[3], b.x, b.y);
                }
            }
        }

        // A(kcn) landed before barrier
        asm volatile("cp.async.wait_group 0;" ::: "memory");

        // ---- BN + ReLU + cvt + STS chunk kcn ----
        if (kcn < NKC) {
            uint32_t* Bn = sm + ((kcn & 1) ? OFF_B1 : OFF_B0);
            const int kcb = kcn * KC;
            #pragma unroll
            for (int j = 0; j < 2; j++) {
                if (j == 0 || v1) {
                    const int c = kcb + (bsk[j] >> 20);
                    float4 s0 = *(const float4*)(sscf + 2 * c);
                    float4 s1 = *(const float4*)(sscf + 2 * (c + 8));
                    float h0 = fmaxf(fmaf(xv[j][0], s0.x, s0.y), 0.0f);
                    float h1 = fmaxf(fmaf(xv[j][1], s0.z, s0.w), 0.0f);
                    float h2 = fmaxf(fmaf(xv[j][2], s1.x, s1.y), 0.0f);
                    float h3 = fmaxf(fmaf(xv[j][3], s1.z, s1.w), 0.0f);
                    uint2 hb;
                    hb.x = pack_h2(h0, h1);
                    hb.y = pack_h2(h2, h3);
                    *(uint2*)(Bn + (bsk[j] & 0xFFFFF)) = hb;
                }
            }
        }
        __syncthreads();
    }

    // ---- epilogue: acc -> SMEM payload P[o][s] -> coalesced vector STG ----
    float* P = (float*)sm;
    {
        const int rb = m0 + g;
        #pragma unroll
        for (int nt = 0; nt < 7; nt++) {
            const int cb = nt * 8 + 2 * t;
            P[rb * PS + cb]           = acc[nt][0];
            P[rb * PS + cb + 1]       = acc[nt][1];
            P[(rb + 8) * PS + cb]     = acc[nt][2];
            P[(rb + 8) * PS + cb + 1] = acc[nt][3];
        }
    }
    __syncthreads();

    float* ob = out + (size_t)blockIdx.x * COUT * HW;
    #pragma unroll
    for (int it = 0; it < 7; it++) {
        int f0 = (tid + it * THREADS) * 4;
        if (f0 < COUT * HW) {
            float4 v;
            #pragma unroll
            for (int e = 0; e < 4; e++) {
                int f = f0 + e;
                int o = f / HW;
                int s = f - o * HW;
                ((float*)&v)[e] = P[o * PS + s];
            }
            *(float4*)(ob + f0) = v;
        }
    }
}

extern "C" void kernel_launch(void* const* d_in, const int* in_sizes, int n_in,
                              void* d_out, int out_size)
{
    const float* x     = (const float*)d_in[0];
    const float* gamma = (const float*)d_in[1];
    const float* beta  = (const float*)d_in[2];
    const float* rmean = (const float*)d_in[3];
    const float* rvar  = (const float*)d_in[4];
    const float* W     = (const float*)d_in[5];
    float* out = (float*)d_out;

    w_cvt_kernel<<<84, 256>>>(W);
    cudaFuncSetAttribute(bn_conv_nb1,
                         cudaFuncAttributeMaxDynamicSharedMemorySize, SMEM_BYTES);
    bn_conv_nb1<<<GRID, THREADS, SMEM_BYTES>>>(x, gamma, beta, rmean, rvar, out);
}

// round 17
// speedup vs baseline: 1.1171x; 1.1171x over previous
#include <cuda_runtime.h>
#include <cuda_fp16.h>
#include <cstdint>

#define CIN   672
#define COUT  128
#define HW    49
#define NB    2
#define NREAL 98          // NB*HW
#define NPAD  112
#define KC    32
#define NKC   21
#define GRID  512
#define THREADS 256

#define LDA 20            // A row stride (half2 words): conflict-free frag reads
#define LDB 24            // B row stride (half2 words)
#define A_WORDS (COUT*LDA)   // 2560
#define B_WORDS (NPAD*LDB)   // 2688

// word offsets in dynamic smem
#define OFF_SS 0                         // float2[672] = 1344 words
#define OFF_TC 1344                      // tables: xoff[4][256] + bsk[4][256] = 2048
#define OFF_A0 (OFF_TC + 2048)           // 3392 ; 3 A buffers
#define OFF_B0 (OFF_A0 + 3*A_WORDS)      // 11072 ; 3 B buffers
#define PIPE_WORDS (OFF_B0 + 3*B_WORDS)  // 19136 words
#define PS 113
#define P_WORDS (COUT*PS)                // 14464 < PIPE_WORDS
#define SMEM_BYTES (PIPE_WORDS*4)        // 76544 B -> 2 CTAs/SM (153KB)

// ---- fp16 copy of W, produced once by K0 ----
__device__ __align__(16) __half W16_buf[COUT * CIN];

__global__ void w_cvt_kernel(const float* __restrict__ W) {
    int i = blockIdx.x * 256 + threadIdx.x;      // 84*256 = 21504 = 86016/4
    float4 v = *(const float4*)(W + i * 4);
    __half2 h0 = __floats2half2_rn(v.x, v.y);
    __half2 h1 = __floats2half2_rn(v.z, v.w);
    uint2 q;
    q.x = *(uint32_t*)&h0;
    q.y = *(uint32_t*)&h1;
    *(uint2*)(W16_buf + i * 4) = q;
}

__device__ __forceinline__ void hmma16816(float c[4],
    uint32_t a0, uint32_t a1, uint32_t a2, uint32_t a3, uint32_t b0, uint32_t b1)
{
    asm volatile(
        "mma.sync.aligned.m16n8k16.row.col.f32.f16.f16.f32 "
        "{%0,%1,%2,%3}, {%4,%5,%6,%7}, {%8,%9}, {%0,%1,%2,%3};"
        : "+f"(c[0]), "+f"(c[1]), "+f"(c[2]), "+f"(c[3])
        : "r"(a0), "r"(a1), "r"(a2), "r"(a3), "r"(b0), "r"(b1));
}
__device__ __forceinline__ uint32_t pack_h2(float lo, float hi) {
    __half2 h = __floats2half2_rn(lo, hi);
    return *reinterpret_cast<uint32_t*>(&h);
}
__device__ __forceinline__ uint32_t smem_u32(const void* p) {
    uint32_t a;
    asm("{ .reg .u64 t; cvta.to.shared.u64 t, %1; cvt.u32.u64 %0, t; }" : "=r"(a) : "l"(p));
    return a;
}
__device__ __forceinline__ void cp16(uint32_t dst, const void* src) {
    asm volatile("cp.async.cg.shared.global [%0], [%1], 16;" :: "r"(dst), "l"(src) : "memory");
}

extern __shared__ uint32_t sm[];

// MMA over one staged chunk (R9-verified fragment math)
__device__ __forceinline__ void mma_chunk(const uint32_t* As, const uint32_t* Bs,
    float acc[2][7][4], int ar00, int ar01, int ar10, int ar11, int bnb, int csl, int t)
{
    #pragma unroll
    for (int ks = 0; ks < 2; ks++) {
        const int ka = ks * 8 + t;
        uint32_t a0[4], a1[4];
        a0[0] = As[ar00 + ka];     a0[1] = As[ar01 + ka];
        a0[2] = As[ar00 + ka + 4]; a0[3] = As[ar01 + ka + 4];
        a1[0] = As[ar10 + ka];     a1[1] = As[ar11 + ka];
        a1[2] = As[ar10 + ka + 4]; a1[3] = As[ar11 + ka + 4];
        const int pr = ks * 4 + t;
        #pragma unroll
        for (int nt = 0; nt < 7; nt++) {
            const int slot = (pr + csl + 2 * nt) & 7;
            uint2 b = *(const uint2*)&Bs[bnb + nt * 8 * LDB + 2 * slot];
            hmma16816(acc[0][nt], a0[0], a0[1], a0[2], a0[3], b.x, b.y);
            hmma16816(acc[1][nt], a1[0], a1[1], a1[2], a1[3], b.x, b.y);
        }
    }
}

__global__ void __launch_bounds__(THREADS, 2)
bn_conv_d2(const float* __restrict__ x,
           const float* __restrict__ gamma,
           const float* __restrict__ beta,
           const float* __restrict__ rmean,
           const float* __restrict__ rvar,
           float* __restrict__ out)
{
    const int tid  = threadIdx.x;
    const int wid  = tid >> 5;
    const int lane = tid & 31;
    const int g = lane >> 2, t = lane & 3;
    const int m0 = (wid & 3) * 32;
    const int n0 = (wid >> 2) * 56;
    const uint32_t sb = smem_u32(sm);

    float2* ssc = (float2*)(sm + OFF_SS);
    const float* sscf = (const float*)ssc;
    int* xofft = (int*)(sm + OFF_TC);          // [4][256]
    int* bskt  = xofft + 1024;                 // [4][256]

    // ---- prologue: BN fold + zero 3 B buffers + const tables ----
    for (int c = tid; c < CIN; c += THREADS) {
        float inv = rsqrtf(rvar[c] + 1e-5f);
        float s = gamma[c] * inv;
        ssc[c] = make_float2(s, beta[c] - rmean[c] * s);
    }
    for (int i = tid; i < 3 * B_WORDS; i += THREADS) sm[OFF_B0 + i] = 0u;

    int xo_r[4], bk_r[4];
    #pragma unroll
    for (int j = 0; j < 4; j++) {
        int i = tid + j * THREADS;
        if (i > 783) i = 783;
        int p = i / 98;
        int n = i - 98 * p;
        int tp = p & 3, ks = p >> 2;
        int kl = ks * 16 + tp * 2;
        int b = (n >= HW) ? 1 : 0;
        int s = n - HW * b;
        xo_r[j] = (b * CIN + kl) * HW + s;
        bk_r[j] = (n * LDB + 2 * ((p + ((n >> 2) & 7)) & 7)) | (kl << 20);
        xofft[j * THREADS + tid] = xo_r[j];
        bskt[j * THREADS + tid]  = bk_r[j];
    }
    const bool v3 = (tid < 16);

    const float* xb = x + (size_t)blockIdx.x * NB * CIN * HW;

    // cp.async A(0), A(1)
    #pragma unroll
    for (int st = 0; st < 2; st++) {
        const uint32_t abase = sb + (OFF_A0 + st * A_WORDS) * 4;
        #pragma unroll
        for (int i = 0; i < 2; i++) {
            int ia = tid + i * THREADS;
            int m = ia >> 2, q = ia & 3;
            cp16(abase + (m * LDA + q * 4) * 4,
                 W16_buf + m * CIN + q * 8 + st * KC);
        }
        asm volatile("cp.async.commit_group;" ::: "memory");
    }

    // LDG x(0) -> xvA, x(1) -> xvB
    float xvA[4][4], xvB[4][4];
    #pragma unroll
    for (int j = 0; j < 4; j++) {
        if (j < 3 || v3) {
            const float* px = xb + xo_r[j];
            xvA[j][0] = px[0];  xvA[j][1] = px[HW];
            xvA[j][2] = px[8 * HW]; xvA[j][3] = px[9 * HW];
            const float* py = px + KC * HW;
            xvB[j][0] = py[0];  xvB[j][1] = py[HW];
            xvB[j][2] = py[8 * HW]; xvB[j][3] = py[9 * HW];
        }
    }
    __syncthreads();   // tables + zeros visible

    // STS B(0) from xvA into Bbuf0
    {
        uint32_t* Bn = sm + OFF_B0;
        #pragma unroll
        for (int j = 0; j < 4; j++) {
            if (j < 3 || v3) {
                const int c = (bk_r[j] >> 20);
                float4 s0 = *(const float4*)(sscf + 2 * c);
                float4 s1 = *(const float4*)(sscf + 2 * (c + 8));
                uint2 hb;
                hb.x = pack_h2(fmaxf(fmaf(xvA[j][0], s0.x, s0.y), 0.0f),
                               fmaxf(fmaf(xvA[j][1], s0.z, s0.w), 0.0f));
                hb.y = pack_h2(fmaxf(fmaf(xvA[j][2], s1.x, s1.y), 0.0f),
                               fmaxf(fmaf(xvA[j][3], s1.z, s1.w), 0.0f));
                *(uint2*)(Bn + (bk_r[j] & 0xFFFFF)) = hb;
            }
        }
    }
    asm volatile("cp.async.wait_group 1;" ::: "memory");   // A(0) done
    __syncthreads();

    float acc[2][7][4];
    #pragma unroll
    for (int mt = 0; mt < 2; mt++)
        #pragma unroll
        for (int nt = 0; nt < 7; nt++)
            #pragma unroll
            for (int i = 0; i < 4; i++) acc[mt][nt][i] = 0.0f;

    const int ar00 = (m0 + g) * LDA;
    const int ar01 = (m0 + g + 8) * LDA;
    const int ar10 = (m0 + 16 + g) * LDA;
    const int ar11 = (m0 + 24 + g) * LDA;
    const int bnb  = (n0 + g) * LDB;
    const int csl  = (n0 >> 2) + (g >> 2);

    // ---- main loop, 2 windows per iteration (xvA/xvB static registers) ----
    #pragma unroll 1
    for (int kc = 0; kc < NKC; kc += 2) {
        // ======== even window: MMA(kc), STS(kc+1)<-xvB, LDG(kc+2)->xvA ========
        {
            const int kp2 = kc + 2;
            // cp.async A(kc+2)
            if (kp2 < NKC) {
                const uint32_t abase = sb + (OFF_A0 + (kp2 % 3) * A_WORDS) * 4;
                #pragma unroll
                for (int i = 0; i < 2; i++) {
                    int ia = tid + i * THREADS;
                    int m = ia >> 2, q = ia & 3;
                    cp16(abase + (m * LDA + q * 4) * 4,
                         W16_buf + m * CIN + q * 8 + kp2 * KC);
                }
            }
            asm volatile("cp.async.commit_group;" ::: "memory");

            // LDG x(kc+2) -> xvA (consumed 2 windows later)
            if (kp2 < NKC) {
                const int xadd = kp2 * (KC * HW);
                #pragma unroll
                for (int j = 0; j < 4; j++) {
                    if (j < 3 || v3) {
                        const float* px = xb + xofft[j * THREADS + tid] + xadd;
                        xvA[j][0] = px[0];  xvA[j][1] = px[HW];
                        xvA[j][2] = px[8 * HW]; xvA[j][3] = px[9 * HW];
                    }
                }
            }

            // MMA(kc)
            mma_chunk(sm + OFF_A0 + (kc % 3) * A_WORDS,
                      sm + OFF_B0 + (kc % 3) * B_WORDS,
                      acc, ar00, ar01, ar10, ar11, bnb, csl, t);

            // STS B(kc+1) from xvB (loaded 2 windows ago)
            if (kc + 1 < NKC) {
                uint32_t* Bn = sm + OFF_B0 + ((kc + 1) % 3) * B_WORDS;
                const int kcb = (kc + 1) * KC;
                #pragma unroll
                for (int j = 0; j < 4; j++) {
                    if (j < 3 || v3) {
                        const int bk = bskt[j * THREADS + tid];
                        const int c = kcb + (bk >> 20);
                        float4 s0 = *(const float4*)(sscf + 2 * c);
                        float4 s1 = *(const float4*)(sscf + 2 * (c + 8));
                        uint2 hb;
                        hb.x = pack_h2(fmaxf(fmaf(xvB[j][0], s0.x, s0.y), 0.0f),
                                       fmaxf(fmaf(xvB[j][1], s0.z, s0.w), 0.0f));
                        hb.y = pack_h2(fmaxf(fmaf(xvB[j][2], s1.x, s1.y), 0.0f),
                                       fmaxf(fmaf(xvB[j][3], s1.z, s1.w), 0.0f));
                        *(uint2*)(Bn + (bk & 0xFFFFF)) = hb;
                    }
                }
            }
            asm volatile("cp.async.wait_group 1;" ::: "memory");
            __syncthreads();
        }

        // ======== odd window: MMA(kc+1), STS(kc+2)<-xvA, LDG(kc+3)->xvB ========
        if (kc + 1 < NKC) {
            const int kk = kc + 1;
            const int kp2 = kk + 2;
            if (kp2 < NKC) {
                const uint32_t abase = sb + (OFF_A0 + (kp2 % 3) * A_WORDS) * 4;
                #pragma unroll
                for (int i = 0; i < 2; i++) {
                    int ia = tid + i * THREADS;
                    int m = ia >> 2, q = ia & 3;
                    cp16(abase + (m * LDA + q * 4) * 4,
                         W16_buf + m * CIN + q * 8 + kp2 * KC);
                }
            }
            asm volatile("cp.async.commit_group;" ::: "memory");

            if (kp2 < NKC) {
                const int xadd = kp2 * (KC * HW);
                #pragma unroll
                for (int j = 0; j < 4; j++) {
                    if (j < 3 || v3) {
                        const float* px = xb + xofft[j * THREADS + tid] + xadd;
                        xvB[j][0] = px[0];  xvB[j][1] = px[HW];
                        xvB[j][2] = px[8 * HW]; xvB[j][3] = px[9 * HW];
                    }
                }
            }

            mma_chunk(sm + OFF_A0 + (kk % 3) * A_WORDS,
                      sm + OFF_B0 + (kk % 3) * B_WORDS,
                      acc, ar00, ar01, ar10, ar11, bnb, csl, t);

            if (kk + 1 < NKC) {
                uint32_t* Bn = sm + OFF_B0 + ((kk + 1) % 3) * B_WORDS;
                const int kcb = (kk + 1) * KC;
                #pragma unroll
                for (int j = 0; j < 4; j++) {
                    if (j < 3 || v3) {
                        const int bk = bskt[j * THREADS + tid];
                        const int c = kcb + (bk >> 20);
                        float4 s0 = *(const float4*)(sscf + 2 * c);
                        float4 s1 = *(const float4*)(sscf + 2 * (c + 8));
                        uint2 hb;
                        hb.x = pack_h2(fmaxf(fmaf(xvA[j][0], s0.x, s0.y), 0.0f),
                                       fmaxf(fmaf(xvA[j][1], s0.z, s0.w), 0.0f));
                        hb.y = pack_h2(fmaxf(fmaf(xvA[j][2], s1.x, s1.y), 0.0f),
                                       fmaxf(fmaf(xvA[j][3], s1.z, s1.w), 0.0f));
                        *(uint2*)(Bn + (bk & 0xFFFFF)) = hb;
                    }
                }
            }
            asm volatile("cp.async.wait_group 1;" ::: "memory");
            __syncthreads();
        }
    }

    // ---- epilogue: acc -> SMEM payload -> coalesced vector STG ----
    float* P = (float*)sm;
    #pragma unroll
    for (int mt = 0; mt < 2; mt++) {
        const int rb = m0 + mt * 16 + g;
        #pragma unroll
        for (int nt = 0; nt < 7; nt++) {
            const int cb = n0 + nt * 8 + 2 * t;
            P[rb * PS + cb]           = acc[mt][nt][0];
            P[rb * PS + cb + 1]       = acc[mt][nt][1];
            P[(rb + 8) * PS + cb]     = acc[mt][nt][2];
            P[(rb + 8) * PS + cb + 1] = acc[mt][nt][3];
        }
    }
    __syncthreads();

    float* ob = out + (size_t)blockIdx.x * NB * COUT * HW;
    #pragma unroll
    for (int it = 0; it < 13; it++) {
        int f0 = (tid + it * THREADS) * 4;
        if (f0 < NB * COUT * HW) {
            float4 v;
            #pragma unroll
            for (int e = 0; e < 4; e++) {
                int f = f0 + e;
                int b = (f >= COUT * HW) ? 1 : 0;
                int r = f - b * (COUT * HW);
                int o = r / HW;
                int s = r - o * HW;
                ((float*)&v)[e] = P[o * PS + b * HW + s];
            }
            *(float4*)(ob + f0) = v;
        }
    }
}

extern "C" void kernel_launch(void* const* d_in, const int* in_sizes, int n_in,
                              void* d_out, int out_size)
{
    const float* x     = (const float*)d_in[0];
    const float* gamma = (const float*)d_in[1];
    const float* beta  = (const float*)d_in[2];
    const float* rmean = (const float*)d_in[3];
    const float* rvar  = (const float*)d_in[4];
    const float* W     = (const float*)d_in[5];
    float* out = (float*)d_out;

    w_cvt_kernel<<<84, 256>>>(W);
    cudaFuncSetAttribute(bn_conv_d2,
                         cudaFuncAttributeMaxDynamicSharedMemorySize, SMEM_BYTES);
    bn_conv_d2<<<GRID, THREADS, SMEM_BYTES>>>(x, gamma, beta, rmean, rvar, out);
}